// round 15
// baseline (speedup 1.0000x reference)
#include <cuda_runtime.h>
#include <cstdint>

#define BATCH 8
#define NPTS  4096
#define MPTS  2048
#define FDIM  64
#define KNBR  64
#define NG    (BATCH*MPTS)
#define CAP   256
#define NTICK (NG/2)
#define NTHR  320

// output segments (float32): x_out [NG,128] | pos_out [NG,3] | batch_out [NG]
#define XSEG   (NG*128)
#define PBASE  XSEG
#define BBASE  (XSEG + NG*3)
#define TOTSEG (BBASE + NG)

__device__ float  g_q[NG*3];
__device__ float4 g_pos4[BATCH*NPTS];
__device__ volatile int g_prog[BATCH];
__device__ int    g_ctr;

typedef unsigned long long u64;

__device__ __forceinline__ unsigned rmax32(unsigned v) {
    unsigned r;
    asm("redux.sync.max.u32 %0, %1, 0xffffffff;" : "=r"(r) : "r"(v));
    return r;
}
__device__ __forceinline__ u64 pk2(float lo, float hi) {
    u64 r; asm("mov.b64 %0, {%1, %2};" : "=l"(r) : "f"(lo), "f"(hi)); return r;
}
__device__ __forceinline__ void up2(u64 v, float& lo, float& hi) {
    asm("mov.b64 {%0, %1}, %2;" : "=f"(lo), "=f"(hi) : "l"(v));
}
__device__ __forceinline__ u64 fma2(u64 a, u64 b, u64 c) {
    u64 r; asm("fma.rn.f32x2 %0, %1, %2, %3;" : "=l"(r) : "l"(a), "l"(b), "l"(c)); return r;
}
__device__ __forceinline__ float ldcv(const float* p) {
    float v; asm volatile("ld.global.cv.f32 %0, [%1];" : "=f"(v) : "l"(p)); return v;
}
__device__ __forceinline__ void barn(int id, int cnt) {
    asm volatile("bar.sync %0, %1;" :: "r"(id), "r"(cnt) : "memory");
}
__device__ __forceinline__ void barr(int id, int cnt) {
    asm volatile("bar.arrive %0, %1;" :: "r"(id), "r"(cnt) : "memory");
}

// ---------------- smem layout (floats) ----------------
#define W1T 0          // 64 x 70   W1t[c*70+k] = W1[k*64+c]
#define W2T 4480       // 64 x 66
#define W3T 8704       // 128 x 66
#define B1O 17152
#define B2O 17216
#define B3O 17280
#define F0  17408      // item0 feat 64x68
#define F1  21760      // item1 feat 64x68
#define H1A 26112      // 64x66
#define H1B 30336
#define H2A 34560
#define H2B 38784
#define RO0 43008      // 16x128
#define RO1 45056
#define CD0 47104      // 256
#define CI0 47360      // 256 int
#define CD1 47616
#define CI1 47872
#define NL0 48128      // 64 int
#define NL1 48192      // 64 int
#define MS  48256      // ints: [1]=cnt0 [2]=cnt1 [4],[5]=ticket slots; floats +8..13 = q0,q1
#define SM_TOT 48272   // 193,088 bytes -> 1 CTA/SM

// ============================================================================
__global__ void __launch_bounds__(256)
init_kernel(const float* __restrict__ pos)
{
    int i = blockIdx.x * 256 + threadIdx.x;
    if (i == 0) g_ctr = 0;
    if (i < BATCH) g_prog[i] = 0;
    if (i < BATCH * NPTS) {
        const float* p = pos + (size_t)i * 3;
        g_pos4[i] = make_float4(p[0], p[1], p[2], 0.0f);
    }
}

// ============================================================================
// prep: spin, radius scan, rank-select, gather (warps 8-9; lt = 0..63)
// ============================================================================
__device__ __forceinline__ void prep_pair(float* sm, const float* __restrict__ x,
                                          int seq, int lt, bool wait)
{
    int*   msi = (int*)(sm + MS);
    float* msf = sm + MS + 8;
    int*   nl0 = (int*)(sm + NL0);
    int*   nl1 = (int*)(sm + NL1);
    int*   ci0 = (int*)(sm + CI0);
    int*   ci1 = (int*)(sm + CI1);
    const int lane = lt & 31;
    const float R2 = (float)(0.15 * 0.15);

    const int b = seq & 7, m0 = (seq >> 3) * 2, m1 = m0 + 1;
    const int g0 = b * MPTS + m0, g1 = g0 + 1;

    if (lt == 0) {
        while (g_prog[b] <= m1) __nanosleep(128);
        __threadfence();
        msf[0] = ldcv(&g_q[3*g0]);
        msf[1] = ldcv(&g_q[3*g0+1]);
        msf[2] = ldcv(&g_q[3*g0+2]);
        msf[3] = ldcv(&g_q[3*g1]);
        msf[4] = ldcv(&g_q[3*g1+1]);
        msf[5] = ldcv(&g_q[3*g1+2]);
        msi[1] = 0; msi[2] = 0;
    }
    barn(2, 64);
    const float q0x = msf[0], q0y = msf[1], q0z = msf[2];
    const float q1x = msf[3], q1y = msf[4], q1z = msf[5];

    // radius scan: one pass, both centroids
#pragma unroll 2
    for (int i = lt; i < NPTS; i += 64) {
        float4 p = g_pos4[b * NPTS + i];
        float dx0 = __fadd_rn(q0x, -p.x);
        float dy0 = __fadd_rn(q0y, -p.y);
        float dz0 = __fadd_rn(q0z, -p.z);
        float d20 = __fadd_rn(__fadd_rn(__fmul_rn(dx0,dx0), __fmul_rn(dy0,dy0)),
                              __fmul_rn(dz0,dz0));
        float dx1 = __fadd_rn(q1x, -p.x);
        float dy1 = __fadd_rn(q1y, -p.y);
        float dz1 = __fadd_rn(q1z, -p.z);
        float d21 = __fadd_rn(__fadd_rn(__fmul_rn(dx1,dx1), __fmul_rn(dy1,dy1)),
                              __fmul_rn(dz1,dz1));
        bool k0 = (d20 <= R2);
        unsigned msk0 = __ballot_sync(0xffffffffu, k0);
        int base0 = 0;
        if (lane == 0 && msk0) base0 = atomicAdd(&msi[1], __popc(msk0));
        base0 = __shfl_sync(0xffffffffu, base0, 0);
        if (k0) {
            int ofs = base0 + __popc(msk0 & ((1u << lane) - 1u));
            if (ofs < CAP) { sm[CD0 + ofs] = d20; ci0[ofs] = i; }
        }
        bool k1 = (d21 <= R2);
        unsigned msk1 = __ballot_sync(0xffffffffu, k1);
        int base1 = 0;
        if (lane == 0 && msk1) base1 = atomicAdd(&msi[2], __popc(msk1));
        base1 = __shfl_sync(0xffffffffu, base1, 0);
        if (k1) {
            int ofs = base1 + __popc(msk1 & ((1u << lane) - 1u));
            if (ofs < CAP) { sm[CD1 + ofs] = d21; ci1[ofs] = i; }
        }
    }
    barn(2, 64);
    int cnt0 = msi[1]; if (cnt0 > CAP) cnt0 = CAP;
    int cnt1 = msi[2]; if (cnt1 > CAP) cnt1 = CAP;

    // rank-select 64 nearest (stable: smaller d2, then lower idx); 32 thr/item
    {
        const int item = lt >> 5, ht = lt & 31;
        const int cnt = item ? cnt1 : cnt0;
        const float* cd = sm + (item ? CD1 : CD0);
        const int* cidx = item ? ci1 : ci0;
        int* nlout = item ? nl1 : nl0;
        if (cnt > KNBR) {
            for (int s = ht; s < cnt; s += 32) {
                float di = cd[s]; int ii = cidx[s];
                int r = 0;
                for (int j2 = 0; j2 < cnt; j2++) {
                    float dj = cd[j2];
                    r += (int)((dj < di) | ((dj == di) & (cidx[j2] < ii)));
                }
                if (r < KNBR) nlout[r] = ii;
            }
        } else {
            for (int s = ht; s < cnt; s += 32) nlout[s] = cidx[s];
        }
    }
    barn(2, 64);
    if (cnt0 > KNBR) cnt0 = KNBR;
    if (cnt1 > KNBR) cnt1 = KNBR;

    if (wait) barn(3, NTHR);    // wait until GEMM finished reading old F (post-L1)

    // gather: thread lt owns row lt of both items
    {
        int j0 = nl0[(lt < cnt0) ? lt : 0];
        int j1 = nl1[(lt < cnt1) ? lt : 0];
        const float4* xr0 = (const float4*)(x + ((size_t)b * NPTS + j0) * FDIM);
        const float4* xr1 = (const float4*)(x + ((size_t)b * NPTS + j1) * FDIM);
        float4* f0 = (float4*)(sm + F0 + lt * 68);
        float4* f1 = (float4*)(sm + F1 + lt * 68);
#pragma unroll
        for (int i = 0; i < 16; i++) f0[i] = xr0[i];
#pragma unroll
        for (int i = 0; i < 16; i++) f1[i] = xr1[i];
        float4 p0 = g_pos4[b * NPTS + j0];
        float4 p1 = g_pos4[b * NPTS + j1];
        sm[F0 + lt*68 + 64] = __fadd_rn(p0.x, -q0x);
        sm[F0 + lt*68 + 65] = __fadd_rn(p0.y, -q0y);
        sm[F0 + lt*68 + 66] = __fadd_rn(p0.z, -q0z);
        sm[F1 + lt*68 + 64] = __fadd_rn(p1.x, -q1x);
        sm[F1 + lt*68 + 65] = __fadd_rn(p1.y, -q1y);
        sm[F1 + lt*68 + 66] = __fadd_rn(p1.z, -q1z);
    }
    // published by the loop-top __syncthreads
}

// ============================================================================
__global__ void __launch_bounds__(NTHR)
fused_kernel(const float* __restrict__ x, const float* __restrict__ pos,
             const float* __restrict__ W1, const float* __restrict__ b1,
             const float* __restrict__ W2, const float* __restrict__ b2,
             const float* __restrict__ W3, const float* __restrict__ b3,
             float* __restrict__ dout, int out_size)
{
    extern __shared__ float sm[];
    const int tid = threadIdx.x;
    const int lane = tid & 31, w = tid >> 5;

    // ======================= producer: FPS (blocks 0..7) ====================
    if (blockIdx.x < BATCH) {
        __shared__ u64 rd2[20];                 // [parity*10 + warp]
        float* sp = sm;                         // [NPTS*4]
        const int b = blockIdx.x;
        const float* pb = pos + (size_t)b * NPTS * 3;

        for (int i = tid; i < NPTS * 3; i += NTHR) {
            int p = i / 3, c = i - 3 * p;
            sp[4 * p + c] = pb[i];
        }
        __syncthreads();

        float px[16], py[16], pz[16], md[16];
        if (tid < 256) {
#pragma unroll
            for (int j = 0; j < 16; j++) {
                int idx = j * 256 + tid;
                px[j] = sp[4*idx]; py[j] = sp[4*idx+1]; pz[j] = sp[4*idx+2];
                md[j] = __int_as_float(0x7f800000);
            }
        }

        if (tid == 0) {
            int g = b * MPTS;
            g_q[3*g] = sp[0]; g_q[3*g+1] = sp[1]; g_q[3*g+2] = sp[2];
            if (out_size >= BBASE) {
                dout[PBASE+3*g] = sp[0]; dout[PBASE+3*g+1] = sp[1]; dout[PBASE+3*g+2] = sp[2];
            }
            if (out_size >= TOTSEG) dout[BBASE+g] = (float)b;
            __threadfence();
            g_prog[b] = 1;
        }

        const float4* sp4 = (const float4*)sp;
        int cur = 0;

        for (int step = 1; step < MPTS; step++) {
            float4 L = sp4[cur];
            float bd = -1.0f; int bi = 0;
            if (tid < 256) {
#pragma unroll
                for (int j = 0; j < 16; j++) {
                    float dx = __fadd_rn(px[j], -L.x);
                    float dy = __fadd_rn(py[j], -L.y);
                    float dz = __fadd_rn(pz[j], -L.z);
                    float d  = __fadd_rn(__fadd_rn(__fmul_rn(dx,dx), __fmul_rn(dy,dy)),
                                         __fmul_rn(dz,dz));
                    float m = fminf(md[j], d);
                    md[j] = m;
                    if (m > bd) { bd = m; bi = j * 256 + tid; }
                }
            }
            unsigned dbits = (tid < 256) ? __float_as_uint(bd) : 0u;
            unsigned mx   = rmax32(dbits);
            unsigned cand = (tid < 256 && dbits == mx)
                          ? (0xFFFFFFFFu - (unsigned)bi) : 0u;
            unsigned cmx  = rmax32(cand);
            if (lane == 0) rd2[(step & 1) * 10 + w] = ((u64)mx << 32) | (u64)cmx;
            __syncthreads();
            const u64* rr = &rd2[(step & 1) * 10];
            u64 best = rr[0];
#pragma unroll
            for (int i = 1; i < 10; i++) { u64 v = rr[i]; if (v > best) best = v; }
            cur = (int)(0xFFFFFFFFu - (unsigned)best);
            if (tid == 0) {
                int g = b * MPTS + step;
                float qx = sp[4*cur], qy = sp[4*cur+1], qz = sp[4*cur+2];
                g_q[3*g] = qx; g_q[3*g+1] = qy; g_q[3*g+2] = qz;
                if (out_size >= BBASE) {
                    dout[PBASE+3*g] = qx; dout[PBASE+3*g+1] = qy; dout[PBASE+3*g+2] = qz;
                }
                if (out_size >= TOTSEG) dout[BBASE+g] = (float)b;
                __threadfence();
                g_prog[b] = step + 1;
            }
        }
        __syncthreads();
    }

    // ======================= stage weights ==================================
    for (int idx = tid; idx < 67 * 64; idx += NTHR) {
        int k = idx >> 6, c = idx & 63;
        sm[W1T + c * 70 + k] = W1[idx];
    }
    for (int idx = tid; idx < 64 * 64; idx += NTHR) {
        int k = idx >> 6, c = idx & 63;
        sm[W2T + c * 66 + k] = W2[idx];
    }
    for (int idx = tid; idx < 64 * 128; idx += NTHR) {
        int k = idx >> 7, c = idx & 127;
        sm[W3T + c * 66 + k] = W3[idx];
    }
    if (tid < 64)  { sm[B1O + tid] = b1[tid]; sm[B2O + tid] = b2[tid]; }
    if (tid < 128)   sm[B3O + tid] = b3[tid];
    __syncthreads();

    int*   msi = (int*)(sm + MS);
    const bool isPrep = (tid >= 256);
    const int lt = tid - 256;
    const int rg = tid >> 4;     // GEMM: rows 4rg..4rg+3 (tid<256)
    const int cg = tid & 15;

    // prologue: prep pair for ticket 0
    if (isPrep) {
        if (lt == 0) msi[4] = atomicAdd(&g_ctr, 1);
        barn(2, 64);
        if (msi[4] < NTICK) prep_pair(sm, x, msi[4], lt, false);
    }

    int it = 0;
    for (;;) {
        __syncthreads();
        const int seq = msi[4 + (it & 1)];
        if (seq >= NTICK) break;
        const int b = seq & 7, m0 = (seq >> 3) * 2;
        const int g0 = b * MPTS + m0, g1 = g0 + 1;

        if (!isPrep) {
            // ---- layer 1 (dual-item, W hoisted): K=67 = 33 k-pairs + tail ----
            {
                u64 acc0[4][4], acc1[4][4];
#pragma unroll
                for (int j = 0; j < 4; j++) {
                    float bb = sm[B1O + cg + 16*j];
#pragma unroll
                    for (int i = 0; i < 4; i++) {
                        acc0[i][j] = pk2(bb, 0.0f);
                        acc1[i][j] = pk2(bb, 0.0f);
                    }
                }
                for (int kp = 0; kp < 33; kp++) {
                    const int k = 2 * kp;
                    u64 a0[4], a1[4];
#pragma unroll
                    for (int i = 0; i < 4; i++) {
                        a0[i] = *(const u64*)(sm + F0 + (4*rg + i)*68 + k);
                        a1[i] = *(const u64*)(sm + F1 + (4*rg + i)*68 + k);
                    }
#pragma unroll
                    for (int j = 0; j < 4; j++) {
                        u64 wv = *(const u64*)(sm + W1T + (cg + 16*j)*70 + k);
#pragma unroll
                        for (int i = 0; i < 4; i++) {
                            acc0[i][j] = fma2(a0[i], wv, acc0[i][j]);
                            acc1[i][j] = fma2(a1[i], wv, acc1[i][j]);
                        }
                    }
                }
#pragma unroll
                for (int i = 0; i < 4; i++) {
                    float a66A = sm[F0 + (4*rg + i)*68 + 66];
                    float a66B = sm[F1 + (4*rg + i)*68 + 66];
#pragma unroll
                    for (int j = 0; j < 4; j++) {
                        float wk = sm[W1T + (cg + 16*j)*70 + 66];
                        float lo, hi;
                        up2(acc0[i][j], lo, hi);
                        float s0 = fmaf(a66A, wk, __fadd_rn(lo, hi));
                        sm[H1A + (4*rg + i)*66 + cg + 16*j] = fmaxf(s0, 0.0f);
                        up2(acc1[i][j], lo, hi);
                        float s1 = fmaf(a66B, wk, __fadd_rn(lo, hi));
                        sm[H1B + (4*rg + i)*66 + cg + 16*j] = fmaxf(s1, 0.0f);
                    }
                }
            }
            barn(1, 256);
            barr(3, NTHR);     // F free for prep's gather

            // ---- layer 2 (dual-item, W hoisted): K=64 ----
            {
                u64 acc0[4][4], acc1[4][4];
#pragma unroll
                for (int j = 0; j < 4; j++) {
                    float bb = sm[B2O + cg + 16*j];
#pragma unroll
                    for (int i = 0; i < 4; i++) {
                        acc0[i][j] = pk2(bb, 0.0f);
                        acc1[i][j] = pk2(bb, 0.0f);
                    }
                }
                for (int kp = 0; kp < 32; kp++) {
                    const int k = 2 * kp;
                    u64 a0[4], a1[4];
#pragma unroll
                    for (int i = 0; i < 4; i++) {
                        a0[i] = *(const u64*)(sm + H1A + (4*rg + i)*66 + k);
                        a1[i] = *(const u64*)(sm + H1B + (4*rg + i)*66 + k);
                    }
#pragma unroll
                    for (int j = 0; j < 4; j++) {
                        u64 wv = *(const u64*)(sm + W2T + (cg + 16*j)*66 + k);
#pragma unroll
                        for (int i = 0; i < 4; i++) {
                            acc0[i][j] = fma2(a0[i], wv, acc0[i][j]);
                            acc1[i][j] = fma2(a1[i], wv, acc1[i][j]);
                        }
                    }
                }
#pragma unroll
                for (int i = 0; i < 4; i++)
#pragma unroll
                    for (int j = 0; j < 4; j++) {
                        float lo, hi;
                        up2(acc0[i][j], lo, hi);
                        sm[H2A + (4*rg + i)*66 + cg + 16*j] = fmaxf(__fadd_rn(lo, hi), 0.0f);
                        up2(acc1[i][j], lo, hi);
                        sm[H2B + (4*rg + i)*66 + cg + 16*j] = fmaxf(__fadd_rn(lo, hi), 0.0f);
                    }
            }
            barn(1, 256);

            // ---- layer 3: per item sequential, K=64 ----
#pragma unroll 1
            for (int itx = 0; itx < 2; itx++) {
                const int hsrc = itx ? H2B : H2A;
                const int rdst = itx ? RO1 : RO0;
                u64 acc[4][8];
#pragma unroll
                for (int j = 0; j < 8; j++) {
                    float bb = sm[B3O + cg + 16*j];
#pragma unroll
                    for (int i = 0; i < 4; i++) acc[i][j] = pk2(bb, 0.0f);
                }
                for (int kp = 0; kp < 32; kp++) {
                    const int k = 2 * kp;
                    u64 a[4];
#pragma unroll
                    for (int i = 0; i < 4; i++)
                        a[i] = *(const u64*)(sm + hsrc + (4*rg + i)*66 + k);
#pragma unroll
                    for (int j = 0; j < 8; j++) {
                        u64 wv = *(const u64*)(sm + W3T + (cg + 16*j)*66 + k);
#pragma unroll
                        for (int i = 0; i < 4; i++)
                            acc[i][j] = fma2(a[i], wv, acc[i][j]);
                    }
                }
#pragma unroll
                for (int j = 0; j < 8; j++) {
                    float lo, hi; up2(acc[0][j], lo, hi);
                    float mm = fmaxf(__fadd_rn(lo, hi), 0.0f);
#pragma unroll
                    for (int i = 1; i < 4; i++) {
                        up2(acc[i][j], lo, hi);
                        mm = fmaxf(mm, fmaxf(__fadd_rn(lo, hi), 0.0f));
                    }
                    sm[rdst + rg*128 + cg + 16*j] = mm;
                }
            }
            barn(1, 256);

            // ---- final reduce + store ----
            {
                const int item = tid >> 7;
                const int ht = tid & 127;
                const int rsrc = item ? RO1 : RO0;
                const int gg = item ? g1 : g0;
                float mm = sm[rsrc + ht];
#pragma unroll
                for (int r = 1; r < 16; r++) mm = fmaxf(mm, sm[rsrc + r*128 + ht]);
                dout[(size_t)gg * 128 + ht] = mm;
            }
        } else {
            // ---- prep warps: fetch + prepare next pair ----
            if (lt == 0) msi[4 + ((it + 1) & 1)] = atomicAdd(&g_ctr, 1);
            barn(2, 64);
            int nseq = msi[4 + ((it + 1) & 1)];
            if (nseq < NTICK) prep_pair(sm, x, nseq, lt, true);
        }
        it++;
    }
}

// ============================================================================
extern "C" void kernel_launch(void* const* d_in, const int* in_sizes, int n_in,
                              void* d_out, int out_size)
{
    const float* x   = (const float*)d_in[0];
    const float* pos = (const float*)d_in[1];
    const float* W1 = (const float*)d_in[3];
    const float* b1 = (const float*)d_in[4];
    const float* W2 = (const float*)d_in[5];
    const float* b2 = (const float*)d_in[6];
    const float* W3 = (const float*)d_in[7];
    const float* b3 = (const float*)d_in[8];
    float* out = (float*)d_out;

    const int fused_smem = SM_TOT * sizeof(float);   // 193,088 B -> 1 CTA/SM
    cudaFuncSetAttribute(fused_kernel, cudaFuncAttributeMaxDynamicSharedMemorySize,
                         fused_smem);

    init_kernel<<<(BATCH * NPTS + 255) / 256, 256>>>(pos);
    fused_kernel<<<148, NTHR, fused_smem>>>(x, pos, W1, b1, W2, b2, W3, b3,
                                            out, out_size);
}